// round 8
// baseline (speedup 1.0000x reference)
#include <cuda_runtime.h>
#include <cuda_fp16.h>
#include <math.h>

#define BB 8
#define NN 2048
#define DD 128
#define TI 64
#define CSHIFT 6.0f

typedef unsigned long long u64;
typedef unsigned int u32;
typedef unsigned short u16;

// -------- scratch --------
__device__ __align__(128) u16 g_Wh_h[BB * NN * DD];    // [b][n][d] fp16 Wh
__device__ float g_e1[BB * NN];
__device__ float g_e2[BB * NN];
__device__ float g_pooled[BB * DD];
__device__ __align__(128) float g_part[2 * 8 * 16 * 128 * 128];  // partial sums (16MB)
__device__ float g_zpart[2 * 8 * 2048];                          // partial Z

// -------- helpers --------
__device__ __forceinline__ u64 pack2(float x, float y) {
    u64 r; asm("mov.b64 %0, {%1,%2};" : "=l"(r) : "f"(x), "f"(y)); return r;
}
__device__ __forceinline__ u64 fma2(u64 a, u64 b, u64 c) {
    u64 d; asm("fma.rn.f32x2 %0, %1, %2, %3;" : "=l"(d) : "l"(a), "l"(b), "l"(c)); return d;
}
__device__ __forceinline__ float2 unpack2(u64 v) {
    float2 r; asm("mov.b64 {%0,%1}, %2;" : "=f"(r.x), "=f"(r.y) : "l"(v)); return r;
}
__device__ __forceinline__ float lrelu(float x) { return x >= 0.f ? x : 0.02f * x; }
__device__ __forceinline__ u32 smem_u32(const void* p) {
    u32 a; asm("{ .reg .u64 t; cvta.to.shared.u64 t, %1; cvt.u32.u64 %0, t; }" : "=r"(a) : "l"(p)); return a;
}
__device__ __forceinline__ void ldsm_x4(u32* r, u32 addr) {
    asm volatile("ldmatrix.sync.aligned.m8n8.x4.shared.b16 {%0,%1,%2,%3}, [%4];"
        : "=r"(r[0]), "=r"(r[1]), "=r"(r[2]), "=r"(r[3]) : "r"(addr));
}
__device__ __forceinline__ void ldsm_x4_t(u32* r, u32 addr) {
    asm volatile("ldmatrix.sync.aligned.m8n8.x4.trans.shared.b16 {%0,%1,%2,%3}, [%4];"
        : "=r"(r[0]), "=r"(r[1]), "=r"(r[2]), "=r"(r[3]) : "r"(addr));
}
__device__ __forceinline__ void mma_f16(float* c, const u32* a, u32 b0, u32 b1) {
    asm volatile("mma.sync.aligned.m16n8k16.row.col.f32.f16.f16.f32 "
        "{%0,%1,%2,%3}, {%4,%5,%6,%7}, {%8,%9}, {%0,%1,%2,%3};"
        : "+f"(c[0]), "+f"(c[1]), "+f"(c[2]), "+f"(c[3])
        : "r"(a[0]), "r"(a[1]), "r"(a[2]), "r"(a[3]), "r"(b0), "r"(b1));
}
__device__ __forceinline__ void cp_async16(u32 dst, const void* src) {
    asm volatile("cp.async.cg.shared.global [%0], [%1], 16;" :: "r"(dst), "l"(src) : "memory");
}
#define CP_COMMIT() asm volatile("cp.async.commit_group;" ::: "memory")
#define CP_WAIT0()  asm volatile("cp.async.wait_group 0;" ::: "memory")

// ============================================================
__global__ void init_pooled_kernel() {
    int t = blockIdx.x * blockDim.x + threadIdx.x;
    if (t < BB * DD) g_pooled[t] = __int_as_float(0xff800000);
}

// ============================================================
// Kernel 1: fc1 + LN + lrelu + Wg GEMM + e1/e2 + fp16 Wh plane
// ============================================================
__global__ void __launch_bounds__(256, 2) fc_kernel(
    const float* __restrict__ h, const float* __restrict__ W1, const float* __restrict__ b1,
    const float* __restrict__ Wg, const float* __restrict__ bg,
    const float* __restrict__ a1, const float* __restrict__ a2)
{
    extern __shared__ float sm[];
    float* Wgs = sm;                    // [128][132]
    float* x_s = Wgs + 128 * 132;       // [64][128]
    float* W1t = x_s + TI * DD;         // [10][128]
    float* h_s = W1t + 1280;            // [64][10]
    float* b1s = h_s + TI * 10;
    float* bgs = b1s + 128;
    float* a1s = bgs + 128;
    float* a2s = a1s + 128;

    int tid = threadIdx.x;
    int warp = tid >> 5, lane = tid & 31;
    int node0 = blockIdx.x * TI;

    #pragma unroll
    for (int it = 0; it < 64; it++) {
        int idx = it * 256 + tid;
        Wgs[(idx & 127) * 132 + (idx >> 7)] = Wg[idx];
    }
    for (int idx = tid; idx < 1280; idx += 256)
        W1t[(idx % 10) * 128 + (idx / 10)] = W1[idx];
    for (int idx = tid; idx < TI * 10; idx += 256)
        h_s[idx] = h[node0 * 10 + idx];
    if (tid < 128) { b1s[tid] = b1[tid]; bgs[tid] = bg[tid]; a1s[tid] = a1[tid]; a2s[tid] = a2[tid]; }
    __syncthreads();

    for (int it = 0; it < 8; it++) {
        int nl = it * 8 + warp;
        float xv[4];
        #pragma unroll
        for (int c = 0; c < 4; c++) xv[c] = b1s[4 * lane + c];
        #pragma unroll
        for (int f = 0; f < 10; f++) {
            float hf = h_s[nl * 10 + f];
            #pragma unroll
            for (int c = 0; c < 4; c++) xv[c] += hf * W1t[f * 128 + 4 * lane + c];
        }
        float s  = xv[0] + xv[1] + xv[2] + xv[3];
        float ss = xv[0]*xv[0] + xv[1]*xv[1] + xv[2]*xv[2] + xv[3]*xv[3];
        #pragma unroll
        for (int o = 16; o > 0; o >>= 1) {
            s  += __shfl_xor_sync(0xffffffffu, s, o);
            ss += __shfl_xor_sync(0xffffffffu, ss, o);
        }
        float m   = s * (1.f / 128.f);
        float var = ss * (1.f / 128.f) - m * m;
        float inv = rsqrtf(var + 1e-5f);
        #pragma unroll
        for (int c = 0; c < 4; c++)
            x_s[nl * DD + 4 * lane + c] = lrelu((xv[c] - m) * inv);
    }
    __syncthreads();

    u64 acc[8][2];
    #pragma unroll
    for (int r = 0; r < 8; r++) { acc[r][0] = 0ull; acc[r][1] = 0ull; }
    for (int kb = 0; kb < 32; kb++) {
        ulonglong2 v[4];
        #pragma unroll
        for (int q = 0; q < 4; q++)
            v[q] = *(const ulonglong2*)(Wgs + (4 * kb + q) * 132 + 4 * lane);
        #pragma unroll
        for (int r = 0; r < 8; r++) {
            float4 w4 = *(const float4*)(x_s + (warp * 8 + r) * DD + 4 * kb);
            u64 w;
            w = pack2(w4.x, w4.x); acc[r][0] = fma2(w, v[0].x, acc[r][0]); acc[r][1] = fma2(w, v[0].y, acc[r][1]);
            w = pack2(w4.y, w4.y); acc[r][0] = fma2(w, v[1].x, acc[r][0]); acc[r][1] = fma2(w, v[1].y, acc[r][1]);
            w = pack2(w4.z, w4.z); acc[r][0] = fma2(w, v[2].x, acc[r][0]); acc[r][1] = fma2(w, v[2].y, acc[r][1]);
            w = pack2(w4.w, w4.w); acc[r][0] = fma2(w, v[3].x, acc[r][0]); acc[r][1] = fma2(w, v[3].y, acc[r][1]);
        }
    }

    #pragma unroll
    for (int r = 0; r < 8; r++) {
        int gn = node0 + warp * 8 + r;
        float2 p0 = unpack2(acc[r][0]);
        float2 p1 = unpack2(acc[r][1]);
        float wv[4];
        wv[0] = p0.x + bgs[4 * lane + 0];
        wv[1] = p0.y + bgs[4 * lane + 1];
        wv[2] = p1.x + bgs[4 * lane + 2];
        wv[3] = p1.y + bgs[4 * lane + 3];
        float d1 = wv[0]*a1s[4*lane] + wv[1]*a1s[4*lane+1] + wv[2]*a1s[4*lane+2] + wv[3]*a1s[4*lane+3];
        float d2 = wv[0]*a2s[4*lane] + wv[1]*a2s[4*lane+1] + wv[2]*a2s[4*lane+2] + wv[3]*a2s[4*lane+3];
        #pragma unroll
        for (int o = 16; o > 0; o >>= 1) {
            d1 += __shfl_xor_sync(0xffffffffu, d1, o);
            d2 += __shfl_xor_sync(0xffffffffu, d2, o);
        }
        if (lane == 0) { g_e1[gn] = d1; g_e2[gn] = d2; }

        u16 hv[4];
        #pragma unroll
        for (int c = 0; c < 4; c++) hv[c] = __half_as_ushort(__float2half_rn(wv[c]));
        u64 hp = (u64)hv[0] | ((u64)hv[1] << 16) | ((u64)hv[2] << 32) | ((u64)hv[3] << 48);
        *(u64*)(g_Wh_h + (size_t)gn * DD + 4 * lane) = hp;
    }
}

// ============================================================
// Kernel 2: attention partials, 2 CTAs/SM, j-split
//   grid (16 iTile, 2 jHalf, 8 b) x 256 threads
// ============================================================
#define BSTRIDE 272
#define SM_WH0  0
#define SM_WH1  34816
#define SM_P    69632
#define SM_E2   104448      /* 1024 f32 */
#define SM_E1   108544      /* 128 f32 */
#define SM_TOTAL 109056
#define SM_HP   0           /* staging overlay [128][132] f32 */

__global__ void __launch_bounds__(256, 2) attn_kernel(const int* __restrict__ adj)
{
    extern __shared__ char smc[];
    u32 sb = smem_u32(smc);

    int tid = threadIdx.x;
    int warp = tid >> 5, lane = tid & 31;
    int b  = blockIdx.z;
    int jh = blockIdx.y;
    int i0 = blockIdx.x * 128;
    int jbase = jh * 1024;

    // e2 half-row + e1 block rows to smem (issued first: oldest in L1tex queue)
    #pragma unroll
    for (int q = 0; q < 4; q++)
        *(float*)(smc + SM_E2 + 4 * (q * 256 + tid)) = g_e2[b * NN + jbase + q * 256 + tid];
    if (tid < 128) *(float*)(smc + SM_E1 + 4 * tid) = g_e1[b * NN + i0 + tid];

    float acc[64];
    #pragma unroll
    for (int q = 0; q < 64; q++) acc[q] = 0.f;
    float zp[16];
    #pragma unroll
    for (int rr = 0; rr < 16; rr++) zp[rr] = 0.f;

    const int* adjb = adj + (size_t)b * NN * NN;
    const u16* Whb  = g_Wh_h + (size_t)b * NN * DD;

    const u32 aOffBase = (u32)(warp * 16 + (lane & 15)) * BSTRIDE + (u32)(((lane >> 4) << 3) * 2);
    const u32 bRowOff  = (u32)(lane & 15) * BSTRIDE;
    const u32 bColOff  = (u32)(((lane >> 4) << 3) * 2);
    const int cpRow0 = tid >> 4;
    const int cpCol8 = (tid & 15) << 3;

    u32 am[16];
    // prologue: Wh tile 0 + adj masks tile 0
    #pragma unroll
    for (int it = 0; it < 8; it++) {
        int row = it * 16 + cpRow0;
        cp_async16(sb + SM_WH0 + (u32)row * BSTRIDE + (u32)cpCol8 * 2,
                   Whb + (size_t)(jbase + row) * DD + cpCol8);
    }
    CP_COMMIT();
    #pragma unroll
    for (int rr = 0; rr < 16; rr++) {
        int4 a = *(const int4*)(adjb + (size_t)(i0 + warp * 16 + rr) * NN + jbase + 4 * lane);
        am[rr] = (a.x != 0 ? 1u : 0u) | (a.y != 0 ? 2u : 0u) | (a.z != 0 ? 4u : 0u) | (a.w != 0 ? 8u : 0u);
    }
    __syncthreads();   // e1/e2 visible

    for (int t = 0; t < 8; t++) {
        int j0 = jbase + t * 128;
        u32 pW = sb + ((t & 1) ? SM_WH1 : SM_WH0);

        // ---- w-gen (P rows warp-private) ----
        __syncwarp();
        float4 e2v = *(const float4*)(smc + SM_E2 + t * 512 + 16 * lane);
        #pragma unroll
        for (int rr = 0; rr < 16; rr++) {
            int il = warp * 16 + rr;
            float e1v = *(const float*)(smc + SM_E1 + 4 * il);
            float w0 = (am[rr] & 1u) ? __expf(lrelu(e1v + e2v.x) - CSHIFT) : 0.f;
            float w1 = (am[rr] & 2u) ? __expf(lrelu(e1v + e2v.y) - CSHIFT) : 0.f;
            float w2 = (am[rr] & 4u) ? __expf(lrelu(e1v + e2v.z) - CSHIFT) : 0.f;
            float w3 = (am[rr] & 8u) ? __expf(lrelu(e1v + e2v.w) - CSHIFT) : 0.f;
            zp[rr] += (w0 + w1) + (w2 + w3);
            __half2 h01 = __floats2half2_rn(w0, w1);
            __half2 h23 = __floats2half2_rn(w2, w3);
            uint2 pk;
            pk.x = *(u32*)&h01; pk.y = *(u32*)&h23;
            *(uint2*)(smc + SM_P + (u32)il * BSTRIDE + (u32)lane * 8) = pk;
        }

        CP_WAIT0();
        __syncthreads();

        // ---- prefetch tile t+1 ----
        if (t < 7) {
            int j1 = j0 + 128;
            u32 pWn = sb + ((t & 1) ? SM_WH0 : SM_WH1);
            #pragma unroll
            for (int it = 0; it < 8; it++) {
                int row = it * 16 + cpRow0;
                cp_async16(pWn + (u32)row * BSTRIDE + (u32)cpCol8 * 2,
                           Whb + (size_t)(j1 + row) * DD + cpCol8);
            }
            CP_COMMIT();
            #pragma unroll
            for (int rr = 0; rr < 16; rr++) {
                int4 a = *(const int4*)(adjb + (size_t)(i0 + warp * 16 + rr) * NN + j1 + 4 * lane);
                am[rr] = (a.x != 0 ? 1u : 0u) | (a.y != 0 ? 2u : 0u) | (a.z != 0 ? 4u : 0u) | (a.w != 0 ? 8u : 0u);
            }
        }

        // ---- MMA ----
        u32 pP = sb + SM_P;
        #pragma unroll
        for (int kk = 0; kk < 8; kk++) {
            u32 afr[4];
            ldsm_x4(afr, pP + aOffBase + (u32)kk * 32);
            #pragma unroll
            for (int nb = 0; nb < 8; nb++) {
                u32 bfr[4];
                ldsm_x4_t(bfr, pW + (u32)(kk * 16) * BSTRIDE + bRowOff + (u32)(nb * 32) + bColOff);
                mma_f16(acc + (2 * nb) * 4,     afr, bfr[0], bfr[1]);
                mma_f16(acc + (2 * nb + 1) * 4, afr, bfr[2], bfr[3]);
            }
        }
    }

    // ---- partial Z to global ----
    #pragma unroll
    for (int rr = 0; rr < 16; rr++) {
        float v = zp[rr];
        #pragma unroll
        for (int o = 16; o > 0; o >>= 1) v += __shfl_xor_sync(0xffffffffu, v, o);
        if (lane == 0) g_zpart[(b * 2 + jh) * NN + i0 + warp * 16 + rr] = v;
    }
    __syncthreads();   // all MMA reads of smem done

    // ---- stage raw acc, coalesced write partials ----
    float* s_hp = (float*)(smc + SM_HP);   // [128][132]
    int rA = warp * 16 + (lane >> 2);
    int rB = rA + 8;
    int c0 = 2 * (lane & 3);
    #pragma unroll
    for (int n8 = 0; n8 < 16; n8++) {
        int col = n8 * 8 + c0;
        s_hp[rA * 132 + col]     = acc[n8 * 4 + 0];
        s_hp[rA * 132 + col + 1] = acc[n8 * 4 + 1];
        s_hp[rB * 132 + col]     = acc[n8 * 4 + 2];
        s_hp[rB * 132 + col + 1] = acc[n8 * 4 + 3];
    }
    __syncthreads();

    float* dst = g_part + ((size_t)((b * 2 + jh) * 16 + blockIdx.x)) * (128 * 128);
    #pragma unroll
    for (int it = 0; it < 16; it++) {
        int idx = it * 1024 + tid * 4;       // float4 granularity
        int row = idx >> 7, col = idx & 127;
        *(float4*)(dst + idx) = *(const float4*)(s_hp + row * 132 + col);
    }
}

// ============================================================
// Kernel 2b: combine halves + LN + lrelu + col-max pool
//   grid (16, 8) x 256
// ============================================================
__global__ void __launch_bounds__(256) combine_kernel()
{
    __shared__ float red[8][128];
    int tid = threadIdx.x;
    int warp = tid >> 5, lane = tid & 31;
    int iT = blockIdx.x, b = blockIdx.y;

    const float* p0 = g_part + ((size_t)((b * 2 + 0) * 16 + iT)) * (128 * 128);
    const float* p1 = g_part + ((size_t)((b * 2 + 1) * 16 + iT)) * (128 * 128);

    float cmax[4] = {-1e30f, -1e30f, -1e30f, -1e30f};
    #pragma unroll
    for (int rr = 0; rr < 16; rr++) {
        int row = warp * 16 + rr;
        float z = g_zpart[(b * 2 + 0) * NN + iT * 128 + row] + g_zpart[(b * 2 + 1) * NN + iT * 128 + row];
        float inv = 1.f / z;
        float4 v0 = *(const float4*)(p0 + row * 128 + 4 * lane);
        float4 v1 = *(const float4*)(p1 + row * 128 + 4 * lane);
        float x0 = (v0.x + v1.x) * inv;
        float x1 = (v0.y + v1.y) * inv;
        float x2 = (v0.z + v1.z) * inv;
        float x3 = (v0.w + v1.w) * inv;
        float s  = (x0 + x1) + (x2 + x3);
        float ss = (x0*x0 + x1*x1) + (x2*x2 + x3*x3);
        #pragma unroll
        for (int o = 16; o > 0; o >>= 1) {
            s  += __shfl_xor_sync(0xffffffffu, s, o);
            ss += __shfl_xor_sync(0xffffffffu, ss, o);
        }
        float m   = s * (1.f / 128.f);
        float var = ss * (1.f / 128.f) - m * m;
        float li  = rsqrtf(var + 1e-5f);
        cmax[0] = fmaxf(cmax[0], lrelu((x0 - m) * li));
        cmax[1] = fmaxf(cmax[1], lrelu((x1 - m) * li));
        cmax[2] = fmaxf(cmax[2], lrelu((x2 - m) * li));
        cmax[3] = fmaxf(cmax[3], lrelu((x3 - m) * li));
    }
    #pragma unroll
    for (int c = 0; c < 4; c++) red[warp][4 * lane + c] = cmax[c];
    __syncthreads();
    if (tid < 128) {
        float v = red[0][tid];
        #pragma unroll
        for (int w = 1; w < 8; w++) v = fmaxf(v, red[w][tid]);
        if (v >= 0.f) atomicMax((int*)&g_pooled[b * DD + tid], __float_as_int(v));
        else          atomicMin((unsigned int*)&g_pooled[b * DD + tid], __float_as_uint(v));
    }
}

// ============================================================
__global__ void final_kernel(const float* __restrict__ W2, const float* __restrict__ b2,
                             float* __restrict__ out)
{
    int warp = threadIdx.x >> 5, lane = threadIdx.x & 31;
    if (warp < BB) {
        float o0 = 0.f, o1 = 0.f;
        #pragma unroll
        for (int c = 0; c < 4; c++) {
            float p = g_pooled[warp * DD + 4 * lane + c];
            o0 += p * W2[4 * lane + c];
            o1 += p * W2[DD + 4 * lane + c];
        }
        #pragma unroll
        for (int o = 16; o > 0; o >>= 1) {
            o0 += __shfl_xor_sync(0xffffffffu, o0, o);
            o1 += __shfl_xor_sync(0xffffffffu, o1, o);
        }
        if (lane == 0) {
            o0 += b2[0]; o1 += b2[1];
            float m = fmaxf(o0, o1);
            float l = m + logf(expf(o0 - m) + expf(o1 - m));
            out[2 * warp + 0] = o0 - l;
            out[2 * warp + 1] = o1 - l;
        }
    }
}

// ============================================================
extern "C" void kernel_launch(void* const* d_in, const int* in_sizes, int n_in,
                              void* d_out, int out_size)
{
    const float* h   = (const float*)d_in[0];
    const int*   adj = (const int*)d_in[1];
    const float* W1  = (const float*)d_in[2];
    const float* b1  = (const float*)d_in[3];
    const float* Wg  = (const float*)d_in[4];
    const float* bg  = (const float*)d_in[5];
    const float* a1  = (const float*)d_in[6];
    const float* a2  = (const float*)d_in[7];
    const float* W2  = (const float*)d_in[8];
    const float* b2  = (const float*)d_in[9];
    float* out = (float*)d_out;

    int smem_fc = (128 * 132 + TI * DD + 1280 + TI * 10 + 4 * 128) * 4;
    int smem_at = SM_TOTAL;
    cudaFuncSetAttribute(fc_kernel,   cudaFuncAttributeMaxDynamicSharedMemorySize, smem_fc);
    cudaFuncSetAttribute(attn_kernel, cudaFuncAttributeMaxDynamicSharedMemorySize, smem_at);

    init_pooled_kernel<<<1, 1024>>>();
    fc_kernel<<<BB * NN / TI, 256, smem_fc>>>(h, W1, b1, Wg, bg, a1, a2);
    attn_kernel<<<dim3(16, 2, BB), 256, smem_at>>>(adj);
    combine_kernel<<<dim3(16, BB), 256>>>();
    final_kernel<<<1, 256>>>(W2, b2, out);
}

// round 12
// speedup vs baseline: 1.4217x; 1.4217x over previous
#include <cuda_runtime.h>
#include <cuda_fp16.h>
#include <math.h>

#define BB 8
#define NN 2048
#define DD 128
#define TI 64
#define CSHIFT 6.0f

typedef unsigned long long u64;
typedef unsigned int u32;
typedef unsigned short u16;

// -------- scratch --------
__device__ __align__(128) u16 g_Wh_h[BB * NN * DD];    // [b][n][d] fp16 Wh
__device__ float g_e1[BB * NN];
__device__ float g_e2[BB * NN];
__device__ float g_pooled[BB * DD];
__device__ __align__(128) float g_part[2 * 8 * 16 * 128 * 128];  // partial sums (16MB)
__device__ float g_zpart[2 * 8 * 2048];                          // partial Z

// -------- helpers --------
__device__ __forceinline__ u64 pack2(float x, float y) {
    u64 r; asm("mov.b64 %0, {%1,%2};" : "=l"(r) : "f"(x), "f"(y)); return r;
}
__device__ __forceinline__ u64 fma2(u64 a, u64 b, u64 c) {
    u64 d; asm("fma.rn.f32x2 %0, %1, %2, %3;" : "=l"(d) : "l"(a), "l"(b), "l"(c)); return d;
}
__device__ __forceinline__ float2 unpack2(u64 v) {
    float2 r; asm("mov.b64 {%0,%1}, %2;" : "=f"(r.x), "=f"(r.y) : "l"(v)); return r;
}
__device__ __forceinline__ float lrelu(float x) { return x >= 0.f ? x : 0.02f * x; }
__device__ __forceinline__ u32 smem_u32(const void* p) {
    u32 a; asm("{ .reg .u64 t; cvta.to.shared.u64 t, %1; cvt.u32.u64 %0, t; }" : "=r"(a) : "l"(p)); return a;
}
__device__ __forceinline__ void ldsm_x4(u32* r, u32 addr) {
    asm volatile("ldmatrix.sync.aligned.m8n8.x4.shared.b16 {%0,%1,%2,%3}, [%4];"
        : "=r"(r[0]), "=r"(r[1]), "=r"(r[2]), "=r"(r[3]) : "r"(addr));
}
__device__ __forceinline__ void ldsm_x4_t(u32* r, u32 addr) {
    asm volatile("ldmatrix.sync.aligned.m8n8.x4.trans.shared.b16 {%0,%1,%2,%3}, [%4];"
        : "=r"(r[0]), "=r"(r[1]), "=r"(r[2]), "=r"(r[3]) : "r"(addr));
}
__device__ __forceinline__ void ldsm_x2_t(u32* r, u32 addr) {
    asm volatile("ldmatrix.sync.aligned.m8n8.x2.trans.shared.b16 {%0,%1}, [%2];"
        : "=r"(r[0]), "=r"(r[1]) : "r"(addr));
}
__device__ __forceinline__ void mma_f16(float* c, const u32* a, u32 b0, u32 b1) {
    asm volatile("mma.sync.aligned.m16n8k16.row.col.f32.f16.f16.f32 "
        "{%0,%1,%2,%3}, {%4,%5,%6,%7}, {%8,%9}, {%0,%1,%2,%3};"
        : "+f"(c[0]), "+f"(c[1]), "+f"(c[2]), "+f"(c[3])
        : "r"(a[0]), "r"(a[1]), "r"(a[2]), "r"(a[3]), "r"(b0), "r"(b1));
}
__device__ __forceinline__ u32 ex2_f16x2(u32 v) {
    u32 r; asm("ex2.approx.f16x2 %0, %1;" : "=r"(r) : "r"(v)); return r;
}
__device__ __forceinline__ void cp_async16(u32 dst, const void* src) {
    asm volatile("cp.async.cg.shared.global [%0], [%1], 16;" :: "r"(dst), "l"(src) : "memory");
}
#define CP_COMMIT() asm volatile("cp.async.commit_group;" ::: "memory")
#define CP_WAIT0()  asm volatile("cp.async.wait_group 0;" ::: "memory")

// ============================================================
__global__ void init_pooled_kernel() {
    int t = blockIdx.x * blockDim.x + threadIdx.x;
    if (t < BB * DD) g_pooled[t] = __int_as_float(0xff800000);
}

// profiling-position filler (4th launch gets profiled -> attn)
__global__ void noop_kernel() {}

// ============================================================
// Kernel 1: fc1 + LN + lrelu + Wg GEMM + e1/e2 + fp16 Wh plane
// ============================================================
__global__ void __launch_bounds__(256, 2) fc_kernel(
    const float* __restrict__ h, const float* __restrict__ W1, const float* __restrict__ b1,
    const float* __restrict__ Wg, const float* __restrict__ bg,
    const float* __restrict__ a1, const float* __restrict__ a2)
{
    extern __shared__ float sm[];
    float* Wgs = sm;                    // [128][132]
    float* x_s = Wgs + 128 * 132;       // [64][128]
    float* W1t = x_s + TI * DD;         // [10][128]
    float* h_s = W1t + 1280;            // [64][10]
    float* b1s = h_s + TI * 10;
    float* bgs = b1s + 128;
    float* a1s = bgs + 128;
    float* a2s = a1s + 128;

    int tid = threadIdx.x;
    int warp = tid >> 5, lane = tid & 31;
    int node0 = blockIdx.x * TI;

    #pragma unroll
    for (int it = 0; it < 64; it++) {
        int idx = it * 256 + tid;
        Wgs[(idx & 127) * 132 + (idx >> 7)] = Wg[idx];
    }
    for (int idx = tid; idx < 1280; idx += 256)
        W1t[(idx % 10) * 128 + (idx / 10)] = W1[idx];
    for (int idx = tid; idx < TI * 10; idx += 256)
        h_s[idx] = h[node0 * 10 + idx];
    if (tid < 128) { b1s[tid] = b1[tid]; bgs[tid] = bg[tid]; a1s[tid] = a1[tid]; a2s[tid] = a2[tid]; }
    __syncthreads();

    for (int it = 0; it < 8; it++) {
        int nl = it * 8 + warp;
        float xv[4];
        #pragma unroll
        for (int c = 0; c < 4; c++) xv[c] = b1s[4 * lane + c];
        #pragma unroll
        for (int f = 0; f < 10; f++) {
            float hf = h_s[nl * 10 + f];
            #pragma unroll
            for (int c = 0; c < 4; c++) xv[c] += hf * W1t[f * 128 + 4 * lane + c];
        }
        float s  = xv[0] + xv[1] + xv[2] + xv[3];
        float ss = xv[0]*xv[0] + xv[1]*xv[1] + xv[2]*xv[2] + xv[3]*xv[3];
        #pragma unroll
        for (int o = 16; o > 0; o >>= 1) {
            s  += __shfl_xor_sync(0xffffffffu, s, o);
            ss += __shfl_xor_sync(0xffffffffu, ss, o);
        }
        float m   = s * (1.f / 128.f);
        float var = ss * (1.f / 128.f) - m * m;
        float inv = rsqrtf(var + 1e-5f);
        #pragma unroll
        for (int c = 0; c < 4; c++)
            x_s[nl * DD + 4 * lane + c] = lrelu((xv[c] - m) * inv);
    }
    __syncthreads();

    u64 acc[8][2];
    #pragma unroll
    for (int r = 0; r < 8; r++) { acc[r][0] = 0ull; acc[r][1] = 0ull; }
    for (int kb = 0; kb < 32; kb++) {
        ulonglong2 v[4];
        #pragma unroll
        for (int q = 0; q < 4; q++)
            v[q] = *(const ulonglong2*)(Wgs + (4 * kb + q) * 132 + 4 * lane);
        #pragma unroll
        for (int r = 0; r < 8; r++) {
            float4 w4 = *(const float4*)(x_s + (warp * 8 + r) * DD + 4 * kb);
            u64 w;
            w = pack2(w4.x, w4.x); acc[r][0] = fma2(w, v[0].x, acc[r][0]); acc[r][1] = fma2(w, v[0].y, acc[r][1]);
            w = pack2(w4.y, w4.y); acc[r][0] = fma2(w, v[1].x, acc[r][0]); acc[r][1] = fma2(w, v[1].y, acc[r][1]);
            w = pack2(w4.z, w4.z); acc[r][0] = fma2(w, v[2].x, acc[r][0]); acc[r][1] = fma2(w, v[2].y, acc[r][1]);
            w = pack2(w4.w, w4.w); acc[r][0] = fma2(w, v[3].x, acc[r][0]); acc[r][1] = fma2(w, v[3].y, acc[r][1]);
        }
    }

    #pragma unroll
    for (int r = 0; r < 8; r++) {
        int gn = node0 + warp * 8 + r;
        float2 p0 = unpack2(acc[r][0]);
        float2 p1 = unpack2(acc[r][1]);
        float wv[4];
        wv[0] = p0.x + bgs[4 * lane + 0];
        wv[1] = p0.y + bgs[4 * lane + 1];
        wv[2] = p1.x + bgs[4 * lane + 2];
        wv[3] = p1.y + bgs[4 * lane + 3];
        float d1 = wv[0]*a1s[4*lane] + wv[1]*a1s[4*lane+1] + wv[2]*a1s[4*lane+2] + wv[3]*a1s[4*lane+3];
        float d2 = wv[0]*a2s[4*lane] + wv[1]*a2s[4*lane+1] + wv[2]*a2s[4*lane+2] + wv[3]*a2s[4*lane+3];
        #pragma unroll
        for (int o = 16; o > 0; o >>= 1) {
            d1 += __shfl_xor_sync(0xffffffffu, d1, o);
            d2 += __shfl_xor_sync(0xffffffffu, d2, o);
        }
        if (lane == 0) { g_e1[gn] = d1; g_e2[gn] = d2; }

        u16 hv[4];
        #pragma unroll
        for (int c = 0; c < 4; c++) hv[c] = __half_as_ushort(__float2half_rn(wv[c]));
        u64 hp = (u64)hv[0] | ((u64)hv[1] << 16) | ((u64)hv[2] << 32) | ((u64)hv[3] << 48);
        *(u64*)(g_Wh_h + (size_t)gn * DD + 4 * lane) = hp;
    }
}

// ============================================================
// Kernel 2: attention partials; Z via ones-column MMA; f16x2 exp
//   grid (16 iTile, 2 jHalf, 8 b) x 256 threads
// ============================================================
#define BSTRIDE 272
#define SM_WH0  0
#define SM_WH1  34816
#define SM_P    69632
#define SM_E2   104448      /* 1024 f32 */
#define SM_E1   108544      /* 128 f32 */
#define SM_TOTAL 109056
#define SM_HP   0           /* staging overlay [128][132] f32 */

__global__ void __launch_bounds__(256, 2) attn_kernel(const int* __restrict__ adj)
{
    extern __shared__ char smc[];
    u32 sb = smem_u32(smc);

    int tid = threadIdx.x;
    int warp = tid >> 5, lane = tid & 31;
    int b  = blockIdx.z;
    int jh = blockIdx.y;
    int i0 = blockIdx.x * 128;
    int jbase = jh * 1024;

    // e2 half-row + e1 block rows to smem
    #pragma unroll
    for (int q = 0; q < 4; q++)
        *(float*)(smc + SM_E2 + 4 * (q * 256 + tid)) = g_e2[b * NN + jbase + q * 256 + tid];
    if (tid < 128) *(float*)(smc + SM_E1 + 4 * tid) = g_e1[b * NN + i0 + tid];

    // static pad-column init (cols 128-135): col128 = 1.0h, rest 0 (both buffers)
    {
        int row = tid & 127;
        u32 buf = (tid >> 7) ? SM_WH1 : SM_WH0;
        uint4 v; v.x = 0x00003C00u; v.y = 0u; v.z = 0u; v.w = 0u;
        *(uint4*)(smc + buf + (u32)row * BSTRIDE + 256) = v;
    }

    float acc[68];
    #pragma unroll
    for (int q = 0; q < 68; q++) acc[q] = 0.f;

    const int* adjb = adj + (size_t)b * NN * NN;
    const u16* Whb  = g_Wh_h + (size_t)b * NN * DD;

    const u32 aOffBase = (u32)(warp * 16 + (lane & 15)) * BSTRIDE + (u32)(((lane >> 4) << 3) * 2);
    const u32 bRowOff  = (u32)(lane & 15) * BSTRIDE;
    const u32 bColOff  = (u32)(((lane >> 4) << 3) * 2);
    const u32 zRowOff  = (u32)(lane & 15) * BSTRIDE + 256;   // ones-column chunk
    const int cpRow0 = tid >> 4;
    const int cpCol8 = (tid & 15) << 3;

    u32 am[16];
    // prologue: Wh tile 0 + adj masks tile 0
    #pragma unroll
    for (int it = 0; it < 8; it++) {
        int row = it * 16 + cpRow0;
        cp_async16(sb + SM_WH0 + (u32)row * BSTRIDE + (u32)cpCol8 * 2,
                   Whb + (size_t)(jbase + row) * DD + cpCol8);
    }
    CP_COMMIT();
    #pragma unroll
    for (int rr = 0; rr < 16; rr++) {
        int4 a = *(const int4*)(adjb + (size_t)(i0 + warp * 16 + rr) * NN + jbase + 4 * lane);
        am[rr] = (a.x != 0 ? 1u : 0u) | (a.y != 0 ? 2u : 0u) | (a.z != 0 ? 4u : 0u) | (a.w != 0 ? 8u : 0u);
    }
    __syncthreads();   // e1/e2 + pad columns visible

    const float L2E  = 1.4426950408889634f;
    const float BIAS = -CSHIFT * L2E;

    for (int t = 0; t < 8; t++) {
        int j0 = jbase + t * 128;
        u32 pW = sb + ((t & 1) ? SM_WH1 : SM_WH0);

        // ---- w-gen (P rows warp-private); f16x2 ex2 ----
        __syncwarp();
        float4 e2v = *(const float4*)(smc + SM_E2 + t * 512 + 16 * lane);
        #pragma unroll
        for (int rr = 0; rr < 16; rr++) {
            int il = warp * 16 + rr;
            float e1v = *(const float*)(smc + SM_E1 + 4 * il);
            float s0 = e1v + e2v.x, s1 = e1v + e2v.y, s2 = e1v + e2v.z, s3 = e1v + e2v.w;
            float t0 = fmaf(fmaxf(s0, 0.02f * s0), L2E, BIAS);
            float t1 = fmaf(fmaxf(s1, 0.02f * s1), L2E, BIAS);
            float t2 = fmaf(fmaxf(s2, 0.02f * s2), L2E, BIAS);
            float t3 = fmaf(fmaxf(s3, 0.02f * s3), L2E, BIAS);
            t0 = (am[rr] & 1u) ? t0 : -30.f;
            t1 = (am[rr] & 2u) ? t1 : -30.f;
            t2 = (am[rr] & 4u) ? t2 : -30.f;
            t3 = (am[rr] & 8u) ? t3 : -30.f;
            __half2 p01 = __floats2half2_rn(t0, t1);
            __half2 p23 = __floats2half2_rn(t2, t3);
            uint2 pk;
            pk.x = ex2_f16x2(*(u32*)&p01);
            pk.y = ex2_f16x2(*(u32*)&p23);
            *(uint2*)(smc + SM_P + (u32)il * BSTRIDE + (u32)lane * 8) = pk;
        }

        CP_WAIT0();
        __syncthreads();

        // ---- prefetch tile t+1 ----
        if (t < 7) {
            int j1 = j0 + 128;
            u32 pWn = sb + ((t & 1) ? SM_WH0 : SM_WH1);
            #pragma unroll
            for (int it = 0; it < 8; it++) {
                int row = it * 16 + cpRow0;
                cp_async16(pWn + (u32)row * BSTRIDE + (u32)cpCol8 * 2,
                           Whb + (size_t)(j1 + row) * DD + cpCol8);
            }
            CP_COMMIT();
            #pragma unroll
            for (int rr = 0; rr < 16; rr++) {
                int4 a = *(const int4*)(adjb + (size_t)(i0 + warp * 16 + rr) * NN + j1 + 4 * lane);
                am[rr] = (a.x != 0 ? 1u : 0u) | (a.y != 0 ? 2u : 0u) | (a.z != 0 ? 4u : 0u) | (a.w != 0 ? 8u : 0u);
            }
        }

        // ---- MMA (8 d-blocks of 16 cols + ones-column block) ----
        u32 pP = sb + SM_P;
        #pragma unroll
        for (int kk = 0; kk < 8; kk++) {
            u32 afr[4];
            ldsm_x4(afr, pP + aOffBase + (u32)kk * 32);
            #pragma unroll
            for (int nb = 0; nb < 8; nb++) {
                u32 bfr[4];
                ldsm_x4_t(bfr, pW + (u32)(kk * 16) * BSTRIDE + bRowOff + (u32)(nb * 32) + bColOff);
                mma_f16(acc + (2 * nb) * 4,     afr, bfr[0], bfr[1]);
                mma_f16(acc + (2 * nb + 1) * 4, afr, bfr[2], bfr[3]);
            }
            u32 zfr[2];
            ldsm_x2_t(zfr, pW + (u32)(kk * 16) * BSTRIDE + zRowOff);
            mma_f16(acc + 64, afr, zfr[0], zfr[1]);
        }
    }

    // ---- partial Z to global (col 128 lives in (lane&3)==0, regs 64/66) ----
    int rA = warp * 16 + (lane >> 2);
    int rB = rA + 8;
    if ((lane & 3) == 0) {
        g_zpart[(b * 2 + jh) * NN + i0 + rA] = acc[64];
        g_zpart[(b * 2 + jh) * NN + i0 + rB] = acc[66];
    }
    __syncthreads();   // all MMA reads of smem done

    // ---- stage raw acc, coalesced write partials ----
    float* s_hp = (float*)(smc + SM_HP);   // [128][132]
    int c0 = 2 * (lane & 3);
    #pragma unroll
    for (int n8 = 0; n8 < 16; n8++) {
        int col = n8 * 8 + c0;
        s_hp[rA * 132 + col]     = acc[n8 * 4 + 0];
        s_hp[rA * 132 + col + 1] = acc[n8 * 4 + 1];
        s_hp[rB * 132 + col]     = acc[n8 * 4 + 2];
        s_hp[rB * 132 + col + 1] = acc[n8 * 4 + 3];
    }
    __syncthreads();

    float* dst = g_part + ((size_t)((b * 2 + jh) * 16 + blockIdx.x)) * (128 * 128);
    #pragma unroll
    for (int it = 0; it < 16; it++) {
        int idx = it * 1024 + tid * 4;
        int row = idx >> 7, col = idx & 127;
        *(float4*)(dst + idx) = *(const float4*)(s_hp + row * 132 + col);
    }
}

// ============================================================
// Kernel 2b: combine halves + LN + lrelu + col-max pool
//   grid (16 iT, 2 rowHalf, 8 b) x 256
// ============================================================
__global__ void __launch_bounds__(256) combine_kernel()
{
    __shared__ float red[8][128];
    int tid = threadIdx.x;
    int warp = tid >> 5, lane = tid & 31;
    int iT = blockIdx.x, rh = blockIdx.y, b = blockIdx.z;

    const float* p0 = g_part + ((size_t)((b * 2 + 0) * 16 + iT)) * (128 * 128);
    const float* p1 = g_part + ((size_t)((b * 2 + 1) * 16 + iT)) * (128 * 128);

    float cmax[4] = {-1e30f, -1e30f, -1e30f, -1e30f};
    #pragma unroll
    for (int rr = 0; rr < 8; rr++) {
        int row = rh * 64 + warp * 8 + rr;
        float z = g_zpart[(b * 2 + 0) * NN + iT * 128 + row] + g_zpart[(b * 2 + 1) * NN + iT * 128 + row];
        float inv = 1.f / z;
        float4 v0 = *(const float4*)(p0 + row * 128 + 4 * lane);
        float4 v1 = *(const float4*)(p1 + row * 128 + 4 * lane);
        float x0 = (v0.x + v1.x) * inv;
        float x1 = (v0.y + v1.y) * inv;
        float x2 = (v0.z + v1.z) * inv;
        float x3 = (v0.w + v1.w) * inv;
        float s  = (x0 + x1) + (x2 + x3);
        float ss = (x0*x0 + x1*x1) + (x2*x2 + x3*x3);
        #pragma unroll
        for (int o = 16; o > 0; o >>= 1) {
            s  += __shfl_xor_sync(0xffffffffu, s, o);
            ss += __shfl_xor_sync(0xffffffffu, ss, o);
        }
        float m   = s * (1.f / 128.f);
        float var = ss * (1.f / 128.f) - m * m;
        float li  = rsqrtf(var + 1e-5f);
        cmax[0] = fmaxf(cmax[0], lrelu((x0 - m) * li));
        cmax[1] = fmaxf(cmax[1], lrelu((x1 - m) * li));
        cmax[2] = fmaxf(cmax[2], lrelu((x2 - m) * li));
        cmax[3] = fmaxf(cmax[3], lrelu((x3 - m) * li));
    }
    #pragma unroll
    for (int c = 0; c < 4; c++) red[warp][4 * lane + c] = cmax[c];
    __syncthreads();
    if (tid < 128) {
        float v = red[0][tid];
        #pragma unroll
        for (int w = 1; w < 8; w++) v = fmaxf(v, red[w][tid]);
        if (v >= 0.f) atomicMax((int*)&g_pooled[b * DD + tid], __float_as_int(v));
        else          atomicMin((unsigned int*)&g_pooled[b * DD + tid], __float_as_uint(v));
    }
}

// ============================================================
__global__ void final_kernel(const float* __restrict__ W2, const float* __restrict__ b2,
                             float* __restrict__ out)
{
    int warp = threadIdx.x >> 5, lane = threadIdx.x & 31;
    if (warp < BB) {
        float o0 = 0.f, o1 = 0.f;
        #pragma unroll
        for (int c = 0; c < 4; c++) {
            float p = g_pooled[warp * DD + 4 * lane + c];
            o0 += p * W2[4 * lane + c];
            o1 += p * W2[DD + 4 * lane + c];
        }
        #pragma unroll
        for (int o = 16; o > 0; o >>= 1) {
            o0 += __shfl_xor_sync(0xffffffffu, o0, o);
            o1 += __shfl_xor_sync(0xffffffffu, o1, o);
        }
        if (lane == 0) {
            o0 += b2[0]; o1 += b2[1];
            float m = fmaxf(o0, o1);
            float l = m + logf(expf(o0 - m) + expf(o1 - m));
            out[2 * warp + 0] = o0 - l;
            out[2 * warp + 1] = o1 - l;
        }
    }
}

// ============================================================
extern "C" void kernel_launch(void* const* d_in, const int* in_sizes, int n_in,
                              void* d_out, int out_size)
{
    const float* h   = (const float*)d_in[0];
    const int*   adj = (const int*)d_in[1];
    const float* W1  = (const float*)d_in[2];
    const float* b1  = (const float*)d_in[3];
    const float* Wg  = (const float*)d_in[4];
    const float* bg  = (const float*)d_in[5];
    const float* a1  = (const float*)d_in[6];
    const float* a2  = (const float*)d_in[7];
    const float* W2  = (const float*)d_in[8];
    const float* b2  = (const float*)d_in[9];
    float* out = (float*)d_out;

    int smem_fc = (128 * 132 + TI * DD + 1280 + TI * 10 + 4 * 128) * 4;
    int smem_at = SM_TOTAL;
    cudaFuncSetAttribute(fc_kernel,   cudaFuncAttributeMaxDynamicSharedMemorySize, smem_fc);
    cudaFuncSetAttribute(attn_kernel, cudaFuncAttributeMaxDynamicSharedMemorySize, smem_at);

    init_pooled_kernel<<<1, 1024>>>();          // launch 1
    fc_kernel<<<BB * NN / TI, 256, smem_fc>>>(h, W1, b1, Wg, bg, a1, a2);  // launch 2
    noop_kernel<<<1, 32>>>();                   // launch 3 (positions attn as profiled 4th)
    attn_kernel<<<dim3(16, 2, BB), 256, smem_at>>>(adj);                   // launch 4
    combine_kernel<<<dim3(16, 2, BB), 256>>>(); // launch 5
    final_kernel<<<1, 256>>>(W2, b2, out);      // launch 6
}

// round 15
// speedup vs baseline: 1.4963x; 1.0525x over previous
#include <cuda_runtime.h>
#include <cuda_fp16.h>
#include <math.h>

#define BB 8
#define NN 2048
#define DD 128
#define TI 64
#define CSHIFT 6.0f

typedef unsigned long long u64;
typedef unsigned int u32;
typedef unsigned short u16;

// -------- scratch --------
__device__ __align__(128) u16 g_Wh_h[BB * NN * DD];    // [b][n][d] fp16 Wh
__device__ float g_e1[BB * NN];
__device__ float g_e2[BB * NN];
__device__ float g_pooled[BB * DD];
__device__ __align__(128) float g_part[2 * 8 * 16 * 128 * 128];  // partial sums (16MB)
__device__ float g_zpart[2 * 8 * 2048];                          // partial Z

// -------- helpers --------
__device__ __forceinline__ u64 pack2(float x, float y) {
    u64 r; asm("mov.b64 %0, {%1,%2};" : "=l"(r) : "f"(x), "f"(y)); return r;
}
__device__ __forceinline__ u64 fma2(u64 a, u64 b, u64 c) {
    u64 d; asm("fma.rn.f32x2 %0, %1, %2, %3;" : "=l"(d) : "l"(a), "l"(b), "l"(c)); return d;
}
__device__ __forceinline__ float2 unpack2(u64 v) {
    float2 r; asm("mov.b64 {%0,%1}, %2;" : "=f"(r.x), "=f"(r.y) : "l"(v)); return r;
}
__device__ __forceinline__ float lrelu(float x) { return x >= 0.f ? x : 0.02f * x; }
__device__ __forceinline__ u32 smem_u32(const void* p) {
    u32 a; asm("{ .reg .u64 t; cvta.to.shared.u64 t, %1; cvt.u32.u64 %0, t; }" : "=r"(a) : "l"(p)); return a;
}
__device__ __forceinline__ void ldsm_x4(u32* r, u32 addr) {
    asm volatile("ldmatrix.sync.aligned.m8n8.x4.shared.b16 {%0,%1,%2,%3}, [%4];"
        : "=r"(r[0]), "=r"(r[1]), "=r"(r[2]), "=r"(r[3]) : "r"(addr));
}
__device__ __forceinline__ void ldsm_x4_t(u32* r, u32 addr) {
    asm volatile("ldmatrix.sync.aligned.m8n8.x4.trans.shared.b16 {%0,%1,%2,%3}, [%4];"
        : "=r"(r[0]), "=r"(r[1]), "=r"(r[2]), "=r"(r[3]) : "r"(addr));
}
__device__ __forceinline__ void ldsm_x2_t(u32* r, u32 addr) {
    asm volatile("ldmatrix.sync.aligned.m8n8.x2.trans.shared.b16 {%0,%1}, [%2];"
        : "=r"(r[0]), "=r"(r[1]) : "r"(addr));
}
__device__ __forceinline__ void mma_f16(float* c, const u32* a, u32 b0, u32 b1) {
    asm volatile("mma.sync.aligned.m16n8k16.row.col.f32.f16.f16.f32 "
        "{%0,%1,%2,%3}, {%4,%5,%6,%7}, {%8,%9}, {%0,%1,%2,%3};"
        : "+f"(c[0]), "+f"(c[1]), "+f"(c[2]), "+f"(c[3])
        : "r"(a[0]), "r"(a[1]), "r"(a[2]), "r"(a[3]), "r"(b0), "r"(b1));
}
__device__ __forceinline__ u32 ex2_f16x2(u32 v) {
    u32 r; asm("ex2.approx.f16x2 %0, %1;" : "=r"(r) : "r"(v)); return r;
}
__device__ __forceinline__ void cp_async16(u32 dst, const void* src) {
    asm volatile("cp.async.cg.shared.global [%0], [%1], 16;" :: "r"(dst), "l"(src) : "memory");
}
#define CP_COMMIT() asm volatile("cp.async.commit_group;" ::: "memory")
#define CP_WAIT0()  asm volatile("cp.async.wait_group 0;" ::: "memory")

// ============================================================
__global__ void init_pooled_kernel() {
    int t = blockIdx.x * blockDim.x + threadIdx.x;
    if (t < BB * DD) g_pooled[t] = __int_as_float(0xff800000);
}

// profiling-position filler (keeps attn as the profiled 4th launch)
__global__ void noop_kernel() {}

// ============================================================
// Kernel 1: fc1 + LN + lrelu + Wg GEMM + e1/e2 + fp16 Wh plane
// ============================================================
__global__ void __launch_bounds__(256, 2) fc_kernel(
    const float* __restrict__ h, const float* __restrict__ W1, const float* __restrict__ b1,
    const float* __restrict__ Wg, const float* __restrict__ bg,
    const float* __restrict__ a1, const float* __restrict__ a2)
{
    extern __shared__ float sm[];
    float* Wgs = sm;                    // [128][132]
    float* x_s = Wgs + 128 * 132;       // [64][128]
    float* W1t = x_s + TI * DD;         // [10][128]
    float* h_s = W1t + 1280;            // [64][10]
    float* b1s = h_s + TI * 10;
    float* bgs = b1s + 128;
    float* a1s = bgs + 128;
    float* a2s = a1s + 128;

    int tid = threadIdx.x;
    int warp = tid >> 5, lane = tid & 31;
    int node0 = blockIdx.x * TI;

    #pragma unroll
    for (int it = 0; it < 64; it++) {
        int idx = it * 256 + tid;
        Wgs[(idx & 127) * 132 + (idx >> 7)] = Wg[idx];
    }
    for (int idx = tid; idx < 1280; idx += 256)
        W1t[(idx % 10) * 128 + (idx / 10)] = W1[idx];
    for (int idx = tid; idx < TI * 10; idx += 256)
        h_s[idx] = h[node0 * 10 + idx];
    if (tid < 128) { b1s[tid] = b1[tid]; bgs[tid] = bg[tid]; a1s[tid] = a1[tid]; a2s[tid] = a2[tid]; }
    __syncthreads();

    for (int it = 0; it < 8; it++) {
        int nl = it * 8 + warp;
        float xv[4];
        #pragma unroll
        for (int c = 0; c < 4; c++) xv[c] = b1s[4 * lane + c];
        #pragma unroll
        for (int f = 0; f < 10; f++) {
            float hf = h_s[nl * 10 + f];
            #pragma unroll
            for (int c = 0; c < 4; c++) xv[c] += hf * W1t[f * 128 + 4 * lane + c];
        }
        float s  = xv[0] + xv[1] + xv[2] + xv[3];
        float ss = xv[0]*xv[0] + xv[1]*xv[1] + xv[2]*xv[2] + xv[3]*xv[3];
        #pragma unroll
        for (int o = 16; o > 0; o >>= 1) {
            s  += __shfl_xor_sync(0xffffffffu, s, o);
            ss += __shfl_xor_sync(0xffffffffu, ss, o);
        }
        float m   = s * (1.f / 128.f);
        float var = ss * (1.f / 128.f) - m * m;
        float inv = rsqrtf(var + 1e-5f);
        #pragma unroll
        for (int c = 0; c < 4; c++)
            x_s[nl * DD + 4 * lane + c] = lrelu((xv[c] - m) * inv);
    }
    __syncthreads();

    u64 acc[8][2];
    #pragma unroll
    for (int r = 0; r < 8; r++) { acc[r][0] = 0ull; acc[r][1] = 0ull; }
    for (int kb = 0; kb < 32; kb++) {
        ulonglong2 v[4];
        #pragma unroll
        for (int q = 0; q < 4; q++)
            v[q] = *(const ulonglong2*)(Wgs + (4 * kb + q) * 132 + 4 * lane);
        #pragma unroll
        for (int r = 0; r < 8; r++) {
            float4 w4 = *(const float4*)(x_s + (warp * 8 + r) * DD + 4 * kb);
            u64 w;
            w = pack2(w4.x, w4.x); acc[r][0] = fma2(w, v[0].x, acc[r][0]); acc[r][1] = fma2(w, v[0].y, acc[r][1]);
            w = pack2(w4.y, w4.y); acc[r][0] = fma2(w, v[1].x, acc[r][0]); acc[r][1] = fma2(w, v[1].y, acc[r][1]);
            w = pack2(w4.z, w4.z); acc[r][0] = fma2(w, v[2].x, acc[r][0]); acc[r][1] = fma2(w, v[2].y, acc[r][1]);
            w = pack2(w4.w, w4.w); acc[r][0] = fma2(w, v[3].x, acc[r][0]); acc[r][1] = fma2(w, v[3].y, acc[r][1]);
        }
    }

    #pragma unroll
    for (int r = 0; r < 8; r++) {
        int gn = node0 + warp * 8 + r;
        float2 p0 = unpack2(acc[r][0]);
        float2 p1 = unpack2(acc[r][1]);
        float wv[4];
        wv[0] = p0.x + bgs[4 * lane + 0];
        wv[1] = p0.y + bgs[4 * lane + 1];
        wv[2] = p1.x + bgs[4 * lane + 2];
        wv[3] = p1.y + bgs[4 * lane + 3];
        float d1 = wv[0]*a1s[4*lane] + wv[1]*a1s[4*lane+1] + wv[2]*a1s[4*lane+2] + wv[3]*a1s[4*lane+3];
        float d2 = wv[0]*a2s[4*lane] + wv[1]*a2s[4*lane+1] + wv[2]*a2s[4*lane+2] + wv[3]*a2s[4*lane+3];
        #pragma unroll
        for (int o = 16; o > 0; o >>= 1) {
            d1 += __shfl_xor_sync(0xffffffffu, d1, o);
            d2 += __shfl_xor_sync(0xffffffffu, d2, o);
        }
        if (lane == 0) { g_e1[gn] = d1; g_e2[gn] = d2; }

        u16 hv[4];
        #pragma unroll
        for (int c = 0; c < 4; c++) hv[c] = __half_as_ushort(__float2half_rn(wv[c]));
        u64 hp = (u64)hv[0] | ((u64)hv[1] << 16) | ((u64)hv[2] << 32) | ((u64)hv[3] << 48);
        *(u64*)(g_Wh_h + (size_t)gn * DD + 4 * lane) = hp;
    }
}

// ============================================================
// Kernel 2: attention partials; Z via ones-column MMA; f16x2 exp;
//   adjacency masks nibble-packed into 2 regs (kills spill pressure)
//   grid (16 iTile, 2 jHalf, 8 b) x 256 threads
// ============================================================
#define BSTRIDE 272
#define SM_WH0  0
#define SM_WH1  34816
#define SM_P    69632
#define SM_E2   104448      /* 1024 f32 */
#define SM_E1   108544      /* 128 f32 */
#define SM_TOTAL 109056
#define SM_HP   0           /* staging overlay [128][132] f32 */

__global__ void __launch_bounds__(256, 2) attn_kernel(const int* __restrict__ adj)
{
    extern __shared__ char smc[];
    u32 sb = smem_u32(smc);

    int tid = threadIdx.x;
    int warp = tid >> 5, lane = tid & 31;
    int b  = blockIdx.z;
    int jh = blockIdx.y;
    int i0 = blockIdx.x * 128;
    int jbase = jh * 1024;

    // e2 half-row + e1 block rows to smem
    #pragma unroll
    for (int q = 0; q < 4; q++)
        *(float*)(smc + SM_E2 + 4 * (q * 256 + tid)) = g_e2[b * NN + jbase + q * 256 + tid];
    if (tid < 128) *(float*)(smc + SM_E1 + 4 * tid) = g_e1[b * NN + i0 + tid];

    // static pad-column init (cols 128-135): col128 = 1.0h, rest 0 (both buffers)
    {
        int row = tid & 127;
        u32 buf = (tid >> 7) ? SM_WH1 : SM_WH0;
        uint4 v; v.x = 0x00003C00u; v.y = 0u; v.z = 0u; v.w = 0u;
        *(uint4*)(smc + buf + (u32)row * BSTRIDE + 256) = v;
    }

    float acc[68];
    #pragma unroll
    for (int q = 0; q < 68; q++) acc[q] = 0.f;

    const int* adjb = adj + (size_t)b * NN * NN;
    const u16* Whb  = g_Wh_h + (size_t)b * NN * DD;

    const u32 aOffBase = (u32)(warp * 16 + (lane & 15)) * BSTRIDE + (u32)(((lane >> 4) << 3) * 2);
    const u32 bRowOff  = (u32)(lane & 15) * BSTRIDE;
    const u32 bColOff  = (u32)(((lane >> 4) << 3) * 2);
    const u32 zRowOff  = (u32)(lane & 15) * BSTRIDE + 256;   // ones-column chunk
    const int cpRow0 = tid >> 4;
    const int cpCol8 = (tid & 15) << 3;

    u32 amLo, amHi;   // nibble-packed adjacency masks: rr 0-7 in amLo, 8-15 in amHi
    // prologue: Wh tile 0 + adj masks tile 0
    #pragma unroll
    for (int it = 0; it < 8; it++) {
        int row = it * 16 + cpRow0;
        cp_async16(sb + SM_WH0 + (u32)row * BSTRIDE + (u32)cpCol8 * 2,
                   Whb + (size_t)(jbase + row) * DD + cpCol8);
    }
    CP_COMMIT();
    {
        u32 lo = 0, hi = 0;
        #pragma unroll
        for (int rr = 0; rr < 16; rr++) {
            int4 a = *(const int4*)(adjb + (size_t)(i0 + warp * 16 + rr) * NN + jbase + 4 * lane);
            u32 m = (a.x != 0 ? 1u : 0u) | (a.y != 0 ? 2u : 0u) | (a.z != 0 ? 4u : 0u) | (a.w != 0 ? 8u : 0u);
            if (rr < 8) lo |= m << (4 * rr); else hi |= m << (4 * (rr - 8));
        }
        amLo = lo; amHi = hi;
    }
    __syncthreads();   // e1/e2 + pad columns visible

    const float L2E  = 1.4426950408889634f;
    const float BIAS = -CSHIFT * L2E;

    for (int t = 0; t < 8; t++) {
        int j0 = jbase + t * 128;
        u32 pW = sb + ((t & 1) ? SM_WH1 : SM_WH0);

        // ---- w-gen (P rows warp-private); f16x2 ex2 ----
        __syncwarp();
        float4 e2v = *(const float4*)(smc + SM_E2 + t * 512 + 16 * lane);
        #pragma unroll
        for (int rr = 0; rr < 16; rr++) {
            int il = warp * 16 + rr;
            u32 bits = (rr < 8 ? (amLo >> (4 * rr)) : (amHi >> (4 * (rr - 8)))) & 0xFu;
            float e1v = *(const float*)(smc + SM_E1 + 4 * il);
            float s0 = e1v + e2v.x, s1 = e1v + e2v.y, s2 = e1v + e2v.z, s3 = e1v + e2v.w;
            float t0 = fmaf(fmaxf(s0, 0.02f * s0), L2E, BIAS);
            float t1 = fmaf(fmaxf(s1, 0.02f * s1), L2E, BIAS);
            float t2 = fmaf(fmaxf(s2, 0.02f * s2), L2E, BIAS);
            float t3 = fmaf(fmaxf(s3, 0.02f * s3), L2E, BIAS);
            t0 = (bits & 1u) ? t0 : -30.f;
            t1 = (bits & 2u) ? t1 : -30.f;
            t2 = (bits & 4u) ? t2 : -30.f;
            t3 = (bits & 8u) ? t3 : -30.f;
            __half2 p01 = __floats2half2_rn(t0, t1);
            __half2 p23 = __floats2half2_rn(t2, t3);
            uint2 pk;
            pk.x = ex2_f16x2(*(u32*)&p01);
            pk.y = ex2_f16x2(*(u32*)&p23);
            *(uint2*)(smc + SM_P + (u32)il * BSTRIDE + (u32)lane * 8) = pk;
        }

        CP_WAIT0();
        __syncthreads();

        // ---- prefetch tile t+1 ----
        if (t < 7) {
            int j1 = j0 + 128;
            u32 pWn = sb + ((t & 1) ? SM_WH0 : SM_WH1);
            #pragma unroll
            for (int it = 0; it < 8; it++) {
                int row = it * 16 + cpRow0;
                cp_async16(pWn + (u32)row * BSTRIDE + (u32)cpCol8 * 2,
                           Whb + (size_t)(j1 + row) * DD + cpCol8);
            }
            CP_COMMIT();
            u32 lo = 0, hi = 0;
            #pragma unroll
            for (int rr = 0; rr < 16; rr++) {
                int4 a = *(const int4*)(adjb + (size_t)(i0 + warp * 16 + rr) * NN + j1 + 4 * lane);
                u32 m = (a.x != 0 ? 1u : 0u) | (a.y != 0 ? 2u : 0u) | (a.z != 0 ? 4u : 0u) | (a.w != 0 ? 8u : 0u);
                if (rr < 8) lo |= m << (4 * rr); else hi |= m << (4 * (rr - 8));
            }
            amLo = lo; amHi = hi;
        }

        // ---- MMA (8 d-blocks of 16 cols + ones-column block) ----
        u32 pP = sb + SM_P;
        #pragma unroll
        for (int kk = 0; kk < 8; kk++) {
            u32 afr[4];
            ldsm_x4(afr, pP + aOffBase + (u32)kk * 32);
            #pragma unroll
            for (int nb = 0; nb < 8; nb++) {
                u32 bfr[4];
                ldsm_x4_t(bfr, pW + (u32)(kk * 16) * BSTRIDE + bRowOff + (u32)(nb * 32) + bColOff);
                mma_f16(acc + (2 * nb) * 4,     afr, bfr[0], bfr[1]);
                mma_f16(acc + (2 * nb + 1) * 4, afr, bfr[2], bfr[3]);
            }
            u32 zfr[2];
            ldsm_x2_t(zfr, pW + (u32)(kk * 16) * BSTRIDE + zRowOff);
            mma_f16(acc + 64, afr, zfr[0], zfr[1]);
        }
    }

    // ---- partial Z to global (col 128 lives in (lane&3)==0, regs 64/66) ----
    int rA = warp * 16 + (lane >> 2);
    int rB = rA + 8;
    if ((lane & 3) == 0) {
        g_zpart[(b * 2 + jh) * NN + i0 + rA] = acc[64];
        g_zpart[(b * 2 + jh) * NN + i0 + rB] = acc[66];
    }
    __syncthreads();   // all MMA reads of smem done

    // ---- stage raw acc, coalesced write partials ----
    float* s_hp = (float*)(smc + SM_HP);   // [128][132]
    int c0 = 2 * (lane & 3);
    #pragma unroll
    for (int n8 = 0; n8 < 16; n8++) {
        int col = n8 * 8 + c0;
        s_hp[rA * 132 + col]     = acc[n8 * 4 + 0];
        s_hp[rA * 132 + col + 1] = acc[n8 * 4 + 1];
        s_hp[rB * 132 + col]     = acc[n8 * 4 + 2];
        s_hp[rB * 132 + col + 1] = acc[n8 * 4 + 3];
    }
    __syncthreads();

    float* dst = g_part + ((size_t)((b * 2 + jh) * 16 + blockIdx.x)) * (128 * 128);
    #pragma unroll
    for (int it = 0; it < 16; it++) {
        int idx = it * 1024 + tid * 4;
        int row = idx >> 7, col = idx & 127;
        *(float4*)(dst + idx) = *(const float4*)(s_hp + row * 132 + col);
    }
}

// ============================================================
// Kernel 2b: combine halves + LN + lrelu + col-max pool
//   grid (16 iT, 4 rowQuarter, 8 b) x 256 — 2x parallelism
// ============================================================
__global__ void __launch_bounds__(256) combine_kernel()
{
    __shared__ float red[8][128];
    int tid = threadIdx.x;
    int warp = tid >> 5, lane = tid & 31;
    int iT = blockIdx.x, rh = blockIdx.y, b = blockIdx.z;

    const float* p0 = g_part + ((size_t)((b * 2 + 0) * 16 + iT)) * (128 * 128);
    const float* p1 = g_part + ((size_t)((b * 2 + 1) * 16 + iT)) * (128 * 128);

    float cmax[4] = {-1e30f, -1e30f, -1e30f, -1e30f};
    #pragma unroll
    for (int rr = 0; rr < 4; rr++) {
        int row = rh * 32 + warp * 4 + rr;
        float z = g_zpart[(b * 2 + 0) * NN + iT * 128 + row] + g_zpart[(b * 2 + 1) * NN + iT * 128 + row];
        float inv = 1.f / z;
        float4 v0 = *(const float4*)(p0 + row * 128 + 4 * lane);
        float4 v1 = *(const float4*)(p1 + row * 128 + 4 * lane);
        float x0 = (v0.x + v1.x) * inv;
        float x1 = (v0.y + v1.y) * inv;
        float x2 = (v0.z + v1.z) * inv;
        float x3 = (v0.w + v1.w) * inv;
        float s  = (x0 + x1) + (x2 + x3);
        float ss = (x0*x0 + x1*x1) + (x2*x2 + x3*x3);
        #pragma unroll
        for (int o = 16; o > 0; o >>= 1) {
            s  += __shfl_xor_sync(0xffffffffu, s, o);
            ss += __shfl_xor_sync(0xffffffffu, ss, o);
        }
        float m   = s * (1.f / 128.f);
        float var = ss * (1.f / 128.f) - m * m;
        float li  = rsqrtf(var + 1e-5f);
        cmax[0] = fmaxf(cmax[0], lrelu((x0 - m) * li));
        cmax[1] = fmaxf(cmax[1], lrelu((x1 - m) * li));
        cmax[2] = fmaxf(cmax[2], lrelu((x2 - m) * li));
        cmax[3] = fmaxf(cmax[3], lrelu((x3 - m) * li));
    }
    #pragma unroll
    for (int c = 0; c < 4; c++) red[warp][4 * lane + c] = cmax[c];
    __syncthreads();
    if (tid < 128) {
        float v = red[0][tid];
        #pragma unroll
        for (int w = 1; w < 8; w++) v = fmaxf(v, red[w][tid]);
        if (v >= 0.f) atomicMax((int*)&g_pooled[b * DD + tid], __float_as_int(v));
        else          atomicMin((unsigned int*)&g_pooled[b * DD + tid], __float_as_uint(v));
    }
}

// ============================================================
__global__ void final_kernel(const float* __restrict__ W2, const float* __restrict__ b2,
                             float* __restrict__ out)
{
    int warp = threadIdx.x >> 5, lane = threadIdx.x & 31;
    if (warp < BB) {
        float o0 = 0.f, o1 = 0.f;
        #pragma unroll
        for (int c = 0; c < 4; c++) {
            float p = g_pooled[warp * DD + 4 * lane + c];
            o0 += p * W2[4 * lane + c];
            o1 += p * W2[DD + 4 * lane + c];
        }
        #pragma unroll
        for (int o = 16; o > 0; o >>= 1) {
            o0 += __shfl_xor_sync(0xffffffffu, o0, o);
            o1 += __shfl_xor_sync(0xffffffffu, o1, o);
        }
        if (lane == 0) {
            o0 += b2[0]; o1 += b2[1];
            float m = fmaxf(o0, o1);
            float l = m + logf(expf(o0 - m) + expf(o1 - m));
            out[2 * warp + 0] = o0 - l;
            out[2 * warp + 1] = o1 - l;
        }
    }
}

// ============================================================
extern "C" void kernel_launch(void* const* d_in, const int* in_sizes, int n_in,
                              void* d_out, int out_size)
{
    const float* h   = (const float*)d_in[0];
    const int*   adj = (const int*)d_in[1];
    const float* W1  = (const float*)d_in[2];
    const float* b1  = (const float*)d_in[3];
    const float* Wg  = (const float*)d_in[4];
    const float* bg  = (const float*)d_in[5];
    const float* a1  = (const float*)d_in[6];
    const float* a2  = (const float*)d_in[7];
    const float* W2  = (const float*)d_in[8];
    const float* b2  = (const float*)d_in[9];
    float* out = (float*)d_out;

    int smem_fc = (128 * 132 + TI * DD + 1280 + TI * 10 + 4 * 128) * 4;
    int smem_at = SM_TOTAL;
    cudaFuncSetAttribute(fc_kernel,   cudaFuncAttributeMaxDynamicSharedMemorySize, smem_fc);
    cudaFuncSetAttribute(attn_kernel, cudaFuncAttributeMaxDynamicSharedMemorySize, smem_at);

    init_pooled_kernel<<<1, 1024>>>();          // launch 1
    fc_kernel<<<BB * NN / TI, 256, smem_fc>>>(h, W1, b1, Wg, bg, a1, a2);  // launch 2
    noop_kernel<<<1, 32>>>();                   // launch 3 (positions attn as profiled 4th)
    attn_kernel<<<dim3(16, 2, BB), 256, smem_at>>>(adj);                   // launch 4
    combine_kernel<<<dim3(16, 4, BB), 256>>>(); // launch 5
    final_kernel<<<1, 256>>>(W2, b2, out);      // launch 6
}